// round 1
// baseline (speedup 1.0000x reference)
#include <cuda_runtime.h>
#include <math.h>

#define NN 50000
#define EE 800000
#define NF 512
#define NH 128
#define NC 16
#define NEG 0.2f
#define FEPS 1e-9f

// ---------------- scratch layout (floats) ----------------
// zeroed-every-launch region first (contiguous):
#define RST1_OFF  ((size_t)0)
#define RST2_OFF  (RST1_OFF + (size_t)NN*NH)          // 6,400,000
#define INDEG_OFF (RST2_OFF + (size_t)NN*NC)          // 7,200,000
#define OUTW1_OFF (INDEG_OFF + NN)
#define INW1_OFF  (OUTW1_OFF + NN)
#define OUTW2_OFF (INW1_OFF + NN)
#define INW2_OFF  (OUTW2_OFF + NN)
#define LOSS_OFF  (INW2_OFF + NN)
#define ZERO_TOTAL (LOSS_OFF + 1)
// non-zeroed region:
#define HLATP_OFF  (((ZERO_TOTAL + 3)/4)*4)
#define HLATP2_OFF (HLATP_OFF + (size_t)NN*NC)
#define H1_OFF     (HLATP2_OFF + (size_t)NN*NC)
#define H2_OFF     (H1_OFF + (size_t)NN*NH)
#define EL1_OFF    (H2_OFF + (size_t)NN*NC)
#define ER1_OFF    (EL1_OFF + NN)
#define EL2_OFF    (ER1_OFF + NN)
#define ER2_OFF    (EL2_OFF + NN)
#define EW_OFF     (ER2_OFF + NN)
#define SC_OFF     (EW_OFF + EE)
#define TOTALF     (SC_OFF + 16)

__device__ __align__(256) float g_s[TOTALF];

__device__ __forceinline__ float elu1(float x){ return x > 0.f ? x : expf(x) - 1.f; }

// ---------------- tiny kernels ----------------

__global__ void k_zero(){
    size_t i = (size_t)blockIdx.x * blockDim.x + threadIdx.x;
    size_t stride = (size_t)gridDim.x * blockDim.x;
    for (; i < ZERO_TOTAL; i += stride) g_s[i] = 0.f;
}

__global__ void k_scalars(const float* b1, const float* a1, const float* t1,
                          const float* b2, const float* a2, const float* t2){
    float* sc = g_s + SC_OFF;
    sc[0] = 2.0f / (expf(-b1[0]) + 1.0f);                  // betaw1
    float e0 = expf(a1[0]), e1 = expf(a1[1]);
    sc[1] = e0 / (e0 + e1); sc[2] = e1 / (e0 + e1);        // softmax(aw1)
    sc[3] = FEPS / (expf(-t1[0]) + 1.0f);                  // perm coeff 1
    sc[4] = 2.0f / (expf(-b2[0]) + 1.0f);
    float f0 = expf(a2[0]), f1 = expf(a2[1]);
    sc[5] = f0 / (f0 + f1); sc[6] = f1 / (f0 + f1);
    sc[7] = FEPS / (expf(-t2[0]) + 1.0f);
}

// out[n,c] = elu( sum_k in[n,k] * W[k,c] + b[c] ),  16x16
__global__ void k_dense16(const float* in_ext, const float* __restrict__ W,
                          const float* __restrict__ bias,
                          size_t in_off, size_t out_off){
    __shared__ float Ws[256];
    __shared__ float bs[16];
    int t = threadIdx.x;
    Ws[t] = W[t];
    if (t < 16) bs[t] = bias[t];
    __syncthreads();
    int idx = blockIdx.x * blockDim.x + t;
    if (idx >= NN * NC) return;
    int n = idx >> 4, c = idx & 15;
    const float* in = in_ext ? (in_ext + (size_t)n * NC) : (g_s + in_off + (size_t)n * NC);
    float acc = bs[c];
#pragma unroll
    for (int k = 0; k < 16; k++) acc = fmaf(in[k], Ws[k * 16 + c], acc);
    g_s[out_off + idx] = elu1(acc);
}

__global__ void k_indeg(const int* __restrict__ dst){
    int e = blockIdx.x * blockDim.x + threadIdx.x;
    if (e < EE) atomicAdd(&g_s[INDEG_OFF + dst[e]], 1.0f);
}

// ---------------- GEMM1: h1 = x (NNxNF) @ fc1_w (NFxNH) ----------------
__global__ __launch_bounds__(256) void k_gemm1(const float* __restrict__ A,
                                               const float* __restrict__ B){
    __shared__ float As[16][132];
    __shared__ float Bs[16][128];
    int tid = threadIdx.x;
    int m0 = blockIdx.x * 128;
    int tx = tid & 15, ty = tid >> 4;
    float acc[8][8];
#pragma unroll
    for (int i = 0; i < 8; i++)
#pragma unroll
        for (int j = 0; j < 8; j++) acc[i][j] = 0.f;

    for (int k0 = 0; k0 < NF; k0 += 16){
#pragma unroll
        for (int l = 0; l < 2; l++){
            int id = tid + l * 256;
            int row = id >> 2, kc = (id & 3) * 4;
            int gm = m0 + row; if (gm >= NN) gm = NN - 1;
            float4 v = *(const float4*)(A + (size_t)gm * NF + k0 + kc);
            As[kc + 0][row] = v.x; As[kc + 1][row] = v.y;
            As[kc + 2][row] = v.z; As[kc + 3][row] = v.w;
        }
#pragma unroll
        for (int l = 0; l < 2; l++){
            int id = tid + l * 256;
            int row = id >> 5, c = (id & 31) * 4;
            float4 v = *(const float4*)(B + (size_t)(k0 + row) * NH + c);
            *(float4*)&Bs[row][c] = v;
        }
        __syncthreads();
#pragma unroll
        for (int kk = 0; kk < 16; kk++){
            float a[8], b[8];
            *(float4*)(a)     = *(float4*)&As[kk][ty * 8];
            *(float4*)(a + 4) = *(float4*)&As[kk][ty * 8 + 4];
            *(float4*)(b)     = *(float4*)&Bs[kk][tx * 8];
            *(float4*)(b + 4) = *(float4*)&Bs[kk][tx * 8 + 4];
#pragma unroll
            for (int i = 0; i < 8; i++)
#pragma unroll
                for (int j = 0; j < 8; j++) acc[i][j] = fmaf(a[i], b[j], acc[i][j]);
        }
        __syncthreads();
    }
#pragma unroll
    for (int i = 0; i < 8; i++){
        int gm = m0 + ty * 8 + i;
        if (gm < NN){
            float* c = g_s + H1_OFF + (size_t)gm * NH + tx * 8;
            *(float4*)c       = make_float4(acc[i][0], acc[i][1], acc[i][2], acc[i][3]);
            *(float4*)(c + 4) = make_float4(acc[i][4], acc[i][5], acc[i][6], acc[i][7]);
        }
    }
}

// ---------------- per-node scalars layer1 (el, er) ----------------
__global__ void k_node1(const float* __restrict__ wu, const float* __restrict__ wv){
    int warp = (blockIdx.x * blockDim.x + threadIdx.x) >> 5;
    int lane = threadIdx.x & 31;
    if (warp >= NN) return;
    const float4* h = (const float4*)(g_s + H1_OFF + (size_t)warp * NH);
    float4 hv = h[lane];
    float4 u4 = ((const float4*)wu)[lane];
    float4 v4 = ((const float4*)wv)[lane];
    float l0 = hv.x > 0.f ? hv.x : NEG * hv.x;
    float l1 = hv.y > 0.f ? hv.y : NEG * hv.y;
    float l2 = hv.z > 0.f ? hv.z : NEG * hv.z;
    float l3 = hv.w > 0.f ? hv.w : NEG * hv.w;
    float u = l0 * u4.x + l1 * u4.y + l2 * u4.z + l3 * u4.w;
    float v = l0 * v4.x + l1 * v4.y + l2 * v4.z + l3 * v4.w;
#pragma unroll
    for (int o = 16; o; o >>= 1){
        u += __shfl_xor_sync(0xffffffffu, u, o);
        v += __shfl_xor_sync(0xffffffffu, v, o);
    }
    if (!lane){ g_s[EL1_OFF + warp] = u; g_s[ER1_OFF + warp] = v; }
}

// ---------------- edge pass 1: compute ew, accumulate outw/inw ----------------
__global__ void k_edge1(const int* __restrict__ src, const int* __restrict__ dst,
                        const float* __restrict__ ws){
    int e = (blockIdx.x * blockDim.x + threadIdx.x) >> 5;
    int lane = threadIdx.x & 31;
    if (e >= EE) return;
    int s = src[e], d = dst[e];
    float4 a = ((const float4*)(g_s + H1_OFF + (size_t)s * NH))[lane];
    float4 b = ((const float4*)(g_s + H1_OFF + (size_t)d * NH))[lane];
    float q, sdf;
    q = a.x - b.x; sdf  = q * q;
    q = a.y - b.y; sdf += q * q;
    q = a.z - b.z; sdf += q * q;
    q = a.w - b.w; sdf += q * q;
    float sds = 0.f, st = 0.f;
    if (lane < NC){
        float fs = g_s[HLATP_OFF + (size_t)s * NC + lane];
        float fd = g_s[HLATP_OFF + (size_t)d * NC + lane];
        float df = fs - fd; sds = df * df;
        st = fs * ws[lane] * fd;
    }
#pragma unroll
    for (int o = 16; o; o >>= 1){
        sdf += __shfl_xor_sync(0xffffffffu, sdf, o);
        sds += __shfl_xor_sync(0xffffffffu, sds, o);
        st  += __shfl_xor_sync(0xffffffffu, st,  o);
    }
    if (!lane){
        const float* sc = g_s + SC_OFF;
        float ev = g_s[EL1_OFF + s] + g_s[ER1_OFF + d] + st;
        float dd = sc[1] * sdf + sc[2] * sds;
        float ew = expf(ev - sc[0] * dd) + FEPS;
        g_s[EW_OFF + e] = ew;
        atomicAdd(&g_s[OUTW1_OFF + s], ew);
        atomicAdd(&g_s[INW1_OFF + d], ew);
    }
}

// ---------------- edge pass 1b: aggregate rst1[dst] += h1[src]*a ----------------
__global__ void k_edge1_agg(const int* __restrict__ src, const int* __restrict__ dst){
    int e = (blockIdx.x * blockDim.x + threadIdx.x) >> 5;
    int lane = threadIdx.x & 31;
    if (e >= EE) return;
    int s = src[e], d = dst[e];
    float aa = rsqrtf(g_s[OUTW1_OFF + s]) * rsqrtf(g_s[INW1_OFF + d]) * g_s[EW_OFF + e];
    float4 hv = ((const float4*)(g_s + H1_OFF + (size_t)s * NH))[lane];
    float* r = g_s + RST1_OFF + (size_t)d * NH + lane * 4;
    atomicAdd(r + 0, hv.x * aa);
    atomicAdd(r + 1, hv.y * aa);
    atomicAdd(r + 2, hv.z * aa);
    atomicAdd(r + 3, hv.w * aa);
}

// ---------------- finalize layer1: rst1 = elu(rst1 + perm*h1) in-place ----------------
__global__ void k_fin1(){
    int i = blockIdx.x * blockDim.x + threadIdx.x;     // over NN*32 float4 chunks
    if (i >= NN * 32) return;
    int n = i >> 5;
    float perm = g_s[SC_OFF + 3] / (g_s[INDEG_OFF + n] + FEPS);
    float4 h = ((const float4*)(g_s + H1_OFF))[i];
    float4 r = ((float4*)(g_s + RST1_OFF))[i];
    r.x = elu1(r.x + h.x * perm);
    r.y = elu1(r.y + h.y * perm);
    r.z = elu1(r.z + h.z * perm);
    r.w = elu1(r.w + h.w * perm);
    ((float4*)(g_s + RST1_OFF))[i] = r;
}

// ---------------- GEMM2: h2 = rst1 (NNxNH) @ fc2_w (NHxNC) ----------------
__global__ void k_gemm2(const float* __restrict__ W){
    __shared__ float Ws[NH * NC];
    for (int i = threadIdx.x; i < NH * NC; i += blockDim.x) Ws[i] = W[i];
    __syncthreads();
    int idx = blockIdx.x * blockDim.x + threadIdx.x;
    if (idx >= NN * NC) return;
    int n = idx >> 4, c = idx & 15;
    const float* h = g_s + RST1_OFF + (size_t)n * NH;
    float acc = 0.f;
#pragma unroll
    for (int k = 0; k < NH; k++) acc = fmaf(h[k], Ws[k * NC + c], acc);
    g_s[H2_OFF + idx] = acc;
}

// ---------------- per-node scalars layer2 ----------------
__global__ void k_node2(const float* __restrict__ wu, const float* __restrict__ wv){
    int n = blockIdx.x * blockDim.x + threadIdx.x;
    if (n >= NN) return;
    const float4* h = (const float4*)(g_s + H2_OFF + (size_t)n * NC);
    const float4* u4 = (const float4*)wu;
    const float4* v4 = (const float4*)wv;
    float u = 0.f, v = 0.f;
#pragma unroll
    for (int j = 0; j < 4; j++){
        float4 a = h[j], uu = u4[j], vv = v4[j];
        float l0 = a.x > 0.f ? a.x : NEG * a.x;
        float l1 = a.y > 0.f ? a.y : NEG * a.y;
        float l2 = a.z > 0.f ? a.z : NEG * a.z;
        float l3 = a.w > 0.f ? a.w : NEG * a.w;
        u += l0 * uu.x + l1 * uu.y + l2 * uu.z + l3 * uu.w;
        v += l0 * vv.x + l1 * vv.y + l2 * vv.z + l3 * vv.w;
    }
    g_s[EL2_OFF + n] = u;
    g_s[ER2_OFF + n] = v;
}

// ---------------- edge pass 2 ----------------
__global__ void k_edge2(const int* __restrict__ src, const int* __restrict__ dst,
                        const float* __restrict__ ws){
    int e = blockIdx.x * blockDim.x + threadIdx.x;
    if (e >= EE) return;
    int s = src[e], d = dst[e];
    const float4* hs = (const float4*)(g_s + H2_OFF + (size_t)s * NC);
    const float4* hd = (const float4*)(g_s + H2_OFF + (size_t)d * NC);
    const float4* fs = (const float4*)(g_s + HLATP2_OFF + (size_t)s * NC);
    const float4* fd = (const float4*)(g_s + HLATP2_OFF + (size_t)d * NC);
    const float4* w4 = (const float4*)ws;
    float sdf = 0.f, sds = 0.f, st = 0.f;
#pragma unroll
    for (int j = 0; j < 4; j++){
        float4 a = hs[j], b = hd[j];
        float q;
        q = a.x - b.x; sdf += q * q;
        q = a.y - b.y; sdf += q * q;
        q = a.z - b.z; sdf += q * q;
        q = a.w - b.w; sdf += q * q;
        float4 p = fs[j], r = fd[j], w = w4[j];
        q = p.x - r.x; sds += q * q;
        q = p.y - r.y; sds += q * q;
        q = p.z - r.z; sds += q * q;
        q = p.w - r.w; sds += q * q;
        st += p.x * w.x * r.x + p.y * w.y * r.y + p.z * w.z * r.z + p.w * w.w * r.w;
    }
    const float* sc = g_s + SC_OFF;
    float ev = g_s[EL2_OFF + s] + g_s[ER2_OFF + d] + st;
    float ew = expf(ev - sc[4] * (sc[5] * sdf + sc[6] * sds)) + FEPS;
    g_s[EW_OFF + e] = ew;
    atomicAdd(&g_s[OUTW2_OFF + s], ew);
    atomicAdd(&g_s[INW2_OFF + d], ew);
}

__global__ void k_edge2_agg(const int* __restrict__ src, const int* __restrict__ dst){
    int e = blockIdx.x * blockDim.x + threadIdx.x;
    if (e >= EE) return;
    int s = src[e], d = dst[e];
    float aa = rsqrtf(g_s[OUTW2_OFF + s]) * rsqrtf(g_s[INW2_OFF + d]) * g_s[EW_OFF + e];
    const float* h = g_s + H2_OFF + (size_t)s * NC;
    float* r = g_s + RST2_OFF + (size_t)d * NC;
#pragma unroll
    for (int c = 0; c < NC; c++) atomicAdd(r + c, h[c] * aa);
}

// ---------------- position loss ----------------
__global__ void k_loss(const int* __restrict__ src, const int* __restrict__ dst,
                       const float* __restrict__ w){
    int e = blockIdx.x * blockDim.x + threadIdx.x;
    float acc = 0.f;
    if (e < EE){
        int s = src[e], d = dst[e];
        const float4* ps = (const float4*)(g_s + HLATP2_OFF + (size_t)s * NC);
        const float4* pd = (const float4*)(g_s + HLATP2_OFF + (size_t)d * NC);
        float dot = 0.f;
#pragma unroll
        for (int j = 0; j < 4; j++){
            float4 a = ps[j], b = pd[j];
            dot += a.x * b.x + a.y * b.y + a.z * b.z + a.w * b.w;
        }
        acc = w[e] * dot;
    }
#pragma unroll
    for (int o = 16; o; o >>= 1) acc += __shfl_xor_sync(0xffffffffu, acc, o);
    if ((threadIdx.x & 31) == 0) atomicAdd(&g_s[LOSS_OFF], acc);
}

// ---------------- final: out = log_softmax(elu(rst2 + perm*h2)) ----------------
__global__ void k_final(float* __restrict__ out, int out_size){
    int n = blockIdx.x * blockDim.x + threadIdx.x;
    if (n == 0 && out_size > NN * NC) out[NN * NC] = g_s[LOSS_OFF];
    if (n >= NN) return;
    float perm = g_s[SC_OFF + 7] / (g_s[INDEG_OFF + n] + FEPS);
    float v[NC];
    float mx = -1e30f;
#pragma unroll
    for (int c = 0; c < NC; c++){
        float t = g_s[RST2_OFF + (size_t)n * NC + c] + g_s[H2_OFF + (size_t)n * NC + c] * perm;
        t = elu1(t);
        v[c] = t;
        mx = fmaxf(mx, t);
    }
    float s = 0.f;
#pragma unroll
    for (int c = 0; c < NC; c++) s += expf(v[c] - mx);
    float lse = mx + logf(s);
#pragma unroll
    for (int c = 0; c < NC; c++) out[(size_t)n * NC + c] = v[c] - lse;
}

// ---------------- launch ----------------
extern "C" void kernel_launch(void* const* d_in, const int* in_sizes, int n_in,
                              void* d_out, int out_size){
    const int*   src    = (const int*)  d_in[0];
    const int*   dst    = (const int*)  d_in[1];
    const float* x      = (const float*)d_in[2];
    const float* weights= (const float*)d_in[3];
    const float* latp   = (const float*)d_in[4];
    const float* sl_w   = (const float*)d_in[5];
    const float* sl_b   = (const float*)d_in[6];
    const float* slo_w  = (const float*)d_in[7];
    const float* slo_b  = (const float*)d_in[8];
    const float* fc1_w  = (const float*)d_in[9];
    const float* w_u1   = (const float*)d_in[10];
    const float* w_v1   = (const float*)d_in[11];
    const float* w_s1   = (const float*)d_in[12];
    const float* beta1  = (const float*)d_in[13];
    const float* aw1    = (const float*)d_in[14];
    const float* theta1 = (const float*)d_in[15];
    const float* fc2_w  = (const float*)d_in[16];
    const float* w_u2   = (const float*)d_in[17];
    const float* w_v2   = (const float*)d_in[18];
    const float* w_s2   = (const float*)d_in[19];
    const float* beta2  = (const float*)d_in[20];
    const float* aw2    = (const float*)d_in[21];
    const float* theta2 = (const float*)d_in[22];
    float* out = (float*)d_out;

    k_zero<<<2048, 256>>>();
    k_scalars<<<1, 1>>>(beta1, aw1, theta1, beta2, aw2, theta2);
    k_dense16<<<(NN * NC + 255) / 256, 256>>>(latp, sl_w, sl_b, (size_t)0, HLATP_OFF);
    k_dense16<<<(NN * NC + 255) / 256, 256>>>(nullptr, slo_w, slo_b, HLATP_OFF, HLATP2_OFF);
    k_gemm1<<<(NN + 127) / 128, 256>>>(x, fc1_w);
    k_indeg<<<(EE + 255) / 256, 256>>>(dst);
    k_node1<<<(NN * 32 + 255) / 256, 256>>>(w_u1, w_v1);
    k_edge1<<<(EE * 32 + 255) / 256 / 1, 256>>>(src, dst, w_s1);
    k_edge1_agg<<<(EE * 32 + 255) / 256, 256>>>(src, dst);
    k_fin1<<<(NN * 32 + 255) / 256, 256>>>();
    k_gemm2<<<(NN * NC + 255) / 256, 256>>>(fc2_w);
    k_node2<<<(NN + 255) / 256, 256>>>(w_u2, w_v2);
    k_edge2<<<(EE + 255) / 256, 256>>>(src, dst, w_s2);
    k_edge2_agg<<<(EE + 255) / 256, 256>>>(src, dst);
    k_loss<<<(EE + 255) / 256, 256>>>(src, dst, weights);
    k_final<<<(NN + 255) / 256, 256>>>(out, out_size);
}

// round 2
// speedup vs baseline: 1.3111x; 1.3111x over previous
#include <cuda_runtime.h>
#include <math.h>

#define NN 50000
#define EE 800000
#define NF 512
#define NH 128
#define NC 16
#define NEG 0.2f
#define FEPS 1e-9f

// ---------------- scratch layout (floats) ----------------
// zeroed-every-launch region first (contiguous):
#define INDEG_OFF ((size_t)0)
#define OUTW1_OFF (INDEG_OFF + NN)
#define INW1_OFF  (OUTW1_OFF + NN)
#define OUTW2_OFF (INW1_OFF + NN)
#define INW2_OFF  (OUTW2_OFF + NN)
#define CUR_OFF   (INW2_OFF + NN)          // int cursor per node
#define LOSS_OFF  (CUR_OFF + NN)
#define ZERO_TOTAL (LOSS_OFF + 1)
// non-zeroed region:
#define HLATP_OFF  (((ZERO_TOTAL + 3)/4)*4)
#define HLATP2_OFF (HLATP_OFF + (size_t)NN*NC)
#define H1_OFF     (HLATP2_OFF + (size_t)NN*NC)
#define H2_OFF     (H1_OFF + (size_t)NN*NH)
#define RST1_OFF   (H2_OFF + (size_t)NN*NC)
#define EL1_OFF    (RST1_OFF + (size_t)NN*NH)
#define ER1_OFF    (EL1_OFF + NN)
#define EL2_OFF    (ER1_OFF + NN)
#define ER2_OFF    (EL2_OFF + NN)
#define EW_OFF     (ER2_OFF + NN)
#define RP_OFF     (EW_OFF + EE)           // int row_ptr[NN+1]
#define EIDX_OFF   (((RP_OFF + NN + 1 + 3)/4)*4)  // int eidx[EE]
#define SC_OFF     (EIDX_OFF + EE)
#define TOTALF     (SC_OFF + 16)

__device__ __align__(256) float g_s[TOTALF];

__device__ __forceinline__ float elu1(float x){ return x > 0.f ? x : expf(x) - 1.f; }

// ---------------- tiny kernels ----------------

__global__ void k_zero(){
    size_t i = (size_t)blockIdx.x * blockDim.x + threadIdx.x;
    size_t stride = (size_t)gridDim.x * blockDim.x;
    for (; i < ZERO_TOTAL; i += stride) g_s[i] = 0.f;
}

__global__ void k_scalars(const float* b1, const float* a1, const float* t1,
                          const float* b2, const float* a2, const float* t2){
    float* sc = g_s + SC_OFF;
    sc[0] = 2.0f / (expf(-b1[0]) + 1.0f);                  // betaw1
    float e0 = expf(a1[0]), e1 = expf(a1[1]);
    sc[1] = e0 / (e0 + e1); sc[2] = e1 / (e0 + e1);        // softmax(aw1)
    sc[3] = FEPS / (expf(-t1[0]) + 1.0f);                  // perm coeff 1
    sc[4] = 2.0f / (expf(-b2[0]) + 1.0f);
    float f0 = expf(a2[0]), f1 = expf(a2[1]);
    sc[5] = f0 / (f0 + f1); sc[6] = f1 / (f0 + f1);
    sc[7] = FEPS / (expf(-t2[0]) + 1.0f);
}

// out[n,c] = elu( sum_k in[n,k] * W[k,c] + b[c] ),  16x16
__global__ void k_dense16(const float* in_ext, const float* __restrict__ W,
                          const float* __restrict__ bias,
                          size_t in_off, size_t out_off){
    __shared__ float Ws[256];
    __shared__ float bs[16];
    int t = threadIdx.x;
    Ws[t] = W[t];
    if (t < 16) bs[t] = bias[t];
    __syncthreads();
    int idx = blockIdx.x * blockDim.x + t;
    if (idx >= NN * NC) return;
    int n = idx >> 4, c = idx & 15;
    const float* in = in_ext ? (in_ext + (size_t)n * NC) : (g_s + in_off + (size_t)n * NC);
    float acc = bs[c];
#pragma unroll
    for (int k = 0; k < 16; k++) acc = fmaf(in[k], Ws[k * 16 + c], acc);
    g_s[out_off + idx] = elu1(acc);
}

__global__ void k_indeg(const int* __restrict__ dst){
    int e = blockIdx.x * blockDim.x + threadIdx.x;
    if (e < EE) atomicAdd(&g_s[INDEG_OFF + dst[e]], 1.0f);
}

// ---------------- prefix scan over in-degrees -> row_ptr (single block) ----------------
__global__ void k_scan(){
    __shared__ int wsum[32];
    __shared__ int carry_s;
    int lane = threadIdx.x & 31, wid = threadIdx.x >> 5;
    if (threadIdx.x == 0) carry_s = 0;
    __syncthreads();
    int* rp = (int*)(g_s + RP_OFF);
    for (int base = 0; base < NN; base += 1024){
        int i = base + threadIdx.x;
        int v = (i < NN) ? (int)g_s[INDEG_OFF + i] : 0;
        int x = v;
#pragma unroll
        for (int o = 1; o < 32; o <<= 1){
            int t = __shfl_up_sync(0xffffffffu, x, o);
            if (lane >= o) x += t;
        }
        if (lane == 31) wsum[wid] = x;
        __syncthreads();
        if (wid == 0){
            int y = wsum[lane];
#pragma unroll
            for (int o = 1; o < 32; o <<= 1){
                int t = __shfl_up_sync(0xffffffffu, y, o);
                if (lane >= o) y += t;
            }
            wsum[lane] = y;
        }
        __syncthreads();
        int incl = x + (wid ? wsum[wid - 1] : 0) + carry_s;
        if (i < NN) rp[i + 1] = incl;
        __syncthreads();
        if (threadIdx.x == 1023) carry_s = incl;
        __syncthreads();
    }
    if (threadIdx.x == 0) rp[0] = 0;
}

__global__ void k_scatter(const int* __restrict__ dst){
    int e = blockIdx.x * blockDim.x + threadIdx.x;
    if (e >= EE) return;
    int d = dst[e];
    int* cur = (int*)(g_s + CUR_OFF);
    const int* rp = (const int*)(g_s + RP_OFF);
    int p = rp[d] + atomicAdd(&cur[d], 1);
    ((int*)(g_s + EIDX_OFF))[p] = e;
}

// ---------------- GEMM1: h1 = x (NNxNF) @ fc1_w (NFxNH) ----------------
__global__ __launch_bounds__(256) void k_gemm1(const float* __restrict__ A,
                                               const float* __restrict__ B){
    __shared__ float As[16][132];
    __shared__ float Bs[16][128];
    int tid = threadIdx.x;
    int m0 = blockIdx.x * 128;
    int tx = tid & 15, ty = tid >> 4;
    float acc[8][8];
#pragma unroll
    for (int i = 0; i < 8; i++)
#pragma unroll
        for (int j = 0; j < 8; j++) acc[i][j] = 0.f;

    for (int k0 = 0; k0 < NF; k0 += 16){
#pragma unroll
        for (int l = 0; l < 2; l++){
            int id = tid + l * 256;
            int row = id >> 2, kc = (id & 3) * 4;
            int gm = m0 + row; if (gm >= NN) gm = NN - 1;
            float4 v = *(const float4*)(A + (size_t)gm * NF + k0 + kc);
            As[kc + 0][row] = v.x; As[kc + 1][row] = v.y;
            As[kc + 2][row] = v.z; As[kc + 3][row] = v.w;
        }
#pragma unroll
        for (int l = 0; l < 2; l++){
            int id = tid + l * 256;
            int row = id >> 5, c = (id & 31) * 4;
            float4 v = *(const float4*)(B + (size_t)(k0 + row) * NH + c);
            *(float4*)&Bs[row][c] = v;
        }
        __syncthreads();
#pragma unroll
        for (int kk = 0; kk < 16; kk++){
            float a[8], b[8];
            *(float4*)(a)     = *(float4*)&As[kk][ty * 8];
            *(float4*)(a + 4) = *(float4*)&As[kk][ty * 8 + 4];
            *(float4*)(b)     = *(float4*)&Bs[kk][tx * 8];
            *(float4*)(b + 4) = *(float4*)&Bs[kk][tx * 8 + 4];
#pragma unroll
            for (int i = 0; i < 8; i++)
#pragma unroll
                for (int j = 0; j < 8; j++) acc[i][j] = fmaf(a[i], b[j], acc[i][j]);
        }
        __syncthreads();
    }
#pragma unroll
    for (int i = 0; i < 8; i++){
        int gm = m0 + ty * 8 + i;
        if (gm < NN){
            float* c = g_s + H1_OFF + (size_t)gm * NH + tx * 8;
            *(float4*)c       = make_float4(acc[i][0], acc[i][1], acc[i][2], acc[i][3]);
            *(float4*)(c + 4) = make_float4(acc[i][4], acc[i][5], acc[i][6], acc[i][7]);
        }
    }
}

// ---------------- per-node scalars layer1 (el, er) ----------------
__global__ void k_node1(const float* __restrict__ wu, const float* __restrict__ wv){
    int warp = (blockIdx.x * blockDim.x + threadIdx.x) >> 5;
    int lane = threadIdx.x & 31;
    if (warp >= NN) return;
    const float4* h = (const float4*)(g_s + H1_OFF + (size_t)warp * NH);
    float4 hv = h[lane];
    float4 u4 = ((const float4*)wu)[lane];
    float4 v4 = ((const float4*)wv)[lane];
    float l0 = hv.x > 0.f ? hv.x : NEG * hv.x;
    float l1 = hv.y > 0.f ? hv.y : NEG * hv.y;
    float l2 = hv.z > 0.f ? hv.z : NEG * hv.z;
    float l3 = hv.w > 0.f ? hv.w : NEG * hv.w;
    float u = l0 * u4.x + l1 * u4.y + l2 * u4.z + l3 * u4.w;
    float v = l0 * v4.x + l1 * v4.y + l2 * v4.z + l3 * v4.w;
#pragma unroll
    for (int o = 16; o; o >>= 1){
        u += __shfl_xor_sync(0xffffffffu, u, o);
        v += __shfl_xor_sync(0xffffffffu, v, o);
    }
    if (!lane){ g_s[EL1_OFF + warp] = u; g_s[ER1_OFF + warp] = v; }
}

// ---------------- edge pass 1: compute ew, accumulate outw/inw ----------------
__global__ void k_edge1(const int* __restrict__ src, const int* __restrict__ dst,
                        const float* __restrict__ ws){
    int e = (blockIdx.x * blockDim.x + threadIdx.x) >> 5;
    int lane = threadIdx.x & 31;
    if (e >= EE) return;
    int s = src[e], d = dst[e];
    float4 a = ((const float4*)(g_s + H1_OFF + (size_t)s * NH))[lane];
    float4 b = ((const float4*)(g_s + H1_OFF + (size_t)d * NH))[lane];
    float q, sdf;
    q = a.x - b.x; sdf  = q * q;
    q = a.y - b.y; sdf += q * q;
    q = a.z - b.z; sdf += q * q;
    q = a.w - b.w; sdf += q * q;
    float sds = 0.f, st = 0.f;
    if (lane < NC){
        float fs = g_s[HLATP_OFF + (size_t)s * NC + lane];
        float fd = g_s[HLATP_OFF + (size_t)d * NC + lane];
        float df = fs - fd; sds = df * df;
        st = fs * ws[lane] * fd;
    }
#pragma unroll
    for (int o = 16; o; o >>= 1){
        sdf += __shfl_xor_sync(0xffffffffu, sdf, o);
        sds += __shfl_xor_sync(0xffffffffu, sds, o);
        st  += __shfl_xor_sync(0xffffffffu, st,  o);
    }
    if (!lane){
        const float* sc = g_s + SC_OFF;
        float ev = g_s[EL1_OFF + s] + g_s[ER1_OFF + d] + st;
        float dd = sc[1] * sdf + sc[2] * sds;
        float ew = expf(ev - sc[0] * dd) + FEPS;
        g_s[EW_OFF + e] = ew;
        atomicAdd(&g_s[OUTW1_OFF + s], ew);
        atomicAdd(&g_s[INW1_OFF + d], ew);
    }
}

// ---------------- CSR aggregation layer1 (fused with perm-residual + elu) ----------------
__global__ void k_agg1(const int* __restrict__ src){
    int d = (blockIdx.x * blockDim.x + threadIdx.x) >> 5;
    int lane = threadIdx.x & 31;
    if (d >= NN) return;
    const int* rp = (const int*)(g_s + RP_OFF);
    const int* eidx = (const int*)(g_s + EIDX_OFF);
    int b = rp[d], eend = rp[d + 1];
    float inw_r = rsqrtf(g_s[INW1_OFF + d]);
    float ax = 0.f, ay = 0.f, az = 0.f, aw = 0.f;
    float bx = 0.f, by = 0.f, bz = 0.f, bw = 0.f;
    int j = b;
    for (; j + 1 < eend; j += 2){
        int e0 = eidx[j], e1 = eidx[j + 1];
        int s0 = src[e0], s1 = src[e1];
        float a0 = inw_r * rsqrtf(g_s[OUTW1_OFF + s0]) * g_s[EW_OFF + e0];
        float a1 = inw_r * rsqrtf(g_s[OUTW1_OFF + s1]) * g_s[EW_OFF + e1];
        float4 h0 = ((const float4*)(g_s + H1_OFF + (size_t)s0 * NH))[lane];
        float4 h1 = ((const float4*)(g_s + H1_OFF + (size_t)s1 * NH))[lane];
        ax = fmaf(h0.x, a0, ax); ay = fmaf(h0.y, a0, ay);
        az = fmaf(h0.z, a0, az); aw = fmaf(h0.w, a0, aw);
        bx = fmaf(h1.x, a1, bx); by = fmaf(h1.y, a1, by);
        bz = fmaf(h1.z, a1, bz); bw = fmaf(h1.w, a1, bw);
    }
    if (j < eend){
        int e0 = eidx[j];
        int s0 = src[e0];
        float a0 = inw_r * rsqrtf(g_s[OUTW1_OFF + s0]) * g_s[EW_OFF + e0];
        float4 h0 = ((const float4*)(g_s + H1_OFF + (size_t)s0 * NH))[lane];
        ax = fmaf(h0.x, a0, ax); ay = fmaf(h0.y, a0, ay);
        az = fmaf(h0.z, a0, az); aw = fmaf(h0.w, a0, aw);
    }
    float perm = g_s[SC_OFF + 3] / (g_s[INDEG_OFF + d] + FEPS);
    float4 hd = ((const float4*)(g_s + H1_OFF + (size_t)d * NH))[lane];
    float4 r;
    r.x = elu1(ax + bx + hd.x * perm);
    r.y = elu1(ay + by + hd.y * perm);
    r.z = elu1(az + bz + hd.z * perm);
    r.w = elu1(aw + bw + hd.w * perm);
    ((float4*)(g_s + RST1_OFF + (size_t)d * NH))[lane] = r;
}

// ---------------- GEMM2: h2 = rst1 (NNxNH) @ fc2_w (NHxNC) ----------------
__global__ void k_gemm2(const float* __restrict__ W){
    __shared__ float Ws[NH * NC];
    for (int i = threadIdx.x; i < NH * NC; i += blockDim.x) Ws[i] = W[i];
    __syncthreads();
    int idx = blockIdx.x * blockDim.x + threadIdx.x;
    if (idx >= NN * NC) return;
    int n = idx >> 4, c = idx & 15;
    const float* h = g_s + RST1_OFF + (size_t)n * NH;
    float acc = 0.f;
#pragma unroll
    for (int k = 0; k < NH; k++) acc = fmaf(h[k], Ws[k * NC + c], acc);
    g_s[H2_OFF + idx] = acc;
}

// ---------------- per-node scalars layer2 ----------------
__global__ void k_node2(const float* __restrict__ wu, const float* __restrict__ wv){
    int n = blockIdx.x * blockDim.x + threadIdx.x;
    if (n >= NN) return;
    const float4* h = (const float4*)(g_s + H2_OFF + (size_t)n * NC);
    const float4* u4 = (const float4*)wu;
    const float4* v4 = (const float4*)wv;
    float u = 0.f, v = 0.f;
#pragma unroll
    for (int j = 0; j < 4; j++){
        float4 a = h[j], uu = u4[j], vv = v4[j];
        float l0 = a.x > 0.f ? a.x : NEG * a.x;
        float l1 = a.y > 0.f ? a.y : NEG * a.y;
        float l2 = a.z > 0.f ? a.z : NEG * a.z;
        float l3 = a.w > 0.f ? a.w : NEG * a.w;
        u += l0 * uu.x + l1 * uu.y + l2 * uu.z + l3 * uu.w;
        v += l0 * vv.x + l1 * vv.y + l2 * vv.z + l3 * vv.w;
    }
    g_s[EL2_OFF + n] = u;
    g_s[ER2_OFF + n] = v;
}

// ---------------- edge pass 2 ----------------
__global__ void k_edge2(const int* __restrict__ src, const int* __restrict__ dst,
                        const float* __restrict__ ws){
    int e = blockIdx.x * blockDim.x + threadIdx.x;
    if (e >= EE) return;
    int s = src[e], d = dst[e];
    const float4* hs = (const float4*)(g_s + H2_OFF + (size_t)s * NC);
    const float4* hd = (const float4*)(g_s + H2_OFF + (size_t)d * NC);
    const float4* fs = (const float4*)(g_s + HLATP2_OFF + (size_t)s * NC);
    const float4* fd = (const float4*)(g_s + HLATP2_OFF + (size_t)d * NC);
    const float4* w4 = (const float4*)ws;
    float sdf = 0.f, sds = 0.f, st = 0.f;
#pragma unroll
    for (int j = 0; j < 4; j++){
        float4 a = hs[j], b = hd[j];
        float q;
        q = a.x - b.x; sdf += q * q;
        q = a.y - b.y; sdf += q * q;
        q = a.z - b.z; sdf += q * q;
        q = a.w - b.w; sdf += q * q;
        float4 p = fs[j], r = fd[j], w = w4[j];
        q = p.x - r.x; sds += q * q;
        q = p.y - r.y; sds += q * q;
        q = p.z - r.z; sds += q * q;
        q = p.w - r.w; sds += q * q;
        st += p.x * w.x * r.x + p.y * w.y * r.y + p.z * w.z * r.z + p.w * w.w * r.w;
    }
    const float* sc = g_s + SC_OFF;
    float ev = g_s[EL2_OFF + s] + g_s[ER2_OFF + d] + st;
    float ew = expf(ev - sc[4] * (sc[5] * sdf + sc[6] * sds)) + FEPS;
    g_s[EW_OFF + e] = ew;
    atomicAdd(&g_s[OUTW2_OFF + s], ew);
    atomicAdd(&g_s[INW2_OFF + d], ew);
}

// ---------------- position loss ----------------
__global__ void k_loss(const int* __restrict__ src, const int* __restrict__ dst,
                       const float* __restrict__ w){
    int e = blockIdx.x * blockDim.x + threadIdx.x;
    float acc = 0.f;
    if (e < EE){
        int s = src[e], d = dst[e];
        const float4* ps = (const float4*)(g_s + HLATP2_OFF + (size_t)s * NC);
        const float4* pd = (const float4*)(g_s + HLATP2_OFF + (size_t)d * NC);
        float dot = 0.f;
#pragma unroll
        for (int j = 0; j < 4; j++){
            float4 a = ps[j], b = pd[j];
            dot += a.x * b.x + a.y * b.y + a.z * b.z + a.w * b.w;
        }
        acc = w[e] * dot;
    }
#pragma unroll
    for (int o = 16; o; o >>= 1) acc += __shfl_xor_sync(0xffffffffu, acc, o);
    if ((threadIdx.x & 31) == 0) atomicAdd(&g_s[LOSS_OFF], acc);
}

// ---------------- CSR aggregation layer2 fused with final log-softmax ----------------
__global__ void k_agg2_final(const int* __restrict__ src, float* __restrict__ out,
                             int out_size){
    int d = (blockIdx.x * blockDim.x + threadIdx.x) >> 5;
    int lane = threadIdx.x & 31;
    if (d >= NN) return;
    if (d == 0 && lane == 0 && out_size > NN * NC) out[NN * NC] = g_s[LOSS_OFF];
    const int* rp = (const int*)(g_s + RP_OFF);
    const int* eidx = (const int*)(g_s + EIDX_OFF);
    int b = rp[d], eend = rp[d + 1];
    int c = lane & 15;
    int half = lane >> 4;           // two half-warps process even/odd edges
    float inw_r = rsqrtf(g_s[INW2_OFF + d]);
    float acc = 0.f;
    for (int j = b + half; j < eend; j += 2){
        int e = eidx[j];
        int s = src[e];
        float a = inw_r * rsqrtf(g_s[OUTW2_OFF + s]) * g_s[EW_OFF + e];
        acc = fmaf(g_s[H2_OFF + (size_t)s * NC + c], a, acc);
    }
    acc += __shfl_xor_sync(0xffffffffu, acc, 16);
    float perm = g_s[SC_OFF + 7] / (g_s[INDEG_OFF + d] + FEPS);
    float t = elu1(acc + g_s[H2_OFF + (size_t)d * NC + c] * perm);
    float mx = t;
#pragma unroll
    for (int o = 8; o; o >>= 1) mx = fmaxf(mx, __shfl_xor_sync(0xffffffffu, mx, o));
    float s2 = expf(t - mx);
#pragma unroll
    for (int o = 8; o; o >>= 1) s2 += __shfl_xor_sync(0xffffffffu, s2, o);
    float lse = mx + logf(s2);
    if (lane < 16) out[(size_t)d * NC + c] = t - lse;
}

// ---------------- launch ----------------
extern "C" void kernel_launch(void* const* d_in, const int* in_sizes, int n_in,
                              void* d_out, int out_size){
    const int*   src    = (const int*)  d_in[0];
    const int*   dst    = (const int*)  d_in[1];
    const float* x      = (const float*)d_in[2];
    const float* weights= (const float*)d_in[3];
    const float* latp   = (const float*)d_in[4];
    const float* sl_w   = (const float*)d_in[5];
    const float* sl_b   = (const float*)d_in[6];
    const float* slo_w  = (const float*)d_in[7];
    const float* slo_b  = (const float*)d_in[8];
    const float* fc1_w  = (const float*)d_in[9];
    const float* w_u1   = (const float*)d_in[10];
    const float* w_v1   = (const float*)d_in[11];
    const float* w_s1   = (const float*)d_in[12];
    const float* beta1  = (const float*)d_in[13];
    const float* aw1    = (const float*)d_in[14];
    const float* theta1 = (const float*)d_in[15];
    const float* fc2_w  = (const float*)d_in[16];
    const float* w_u2   = (const float*)d_in[17];
    const float* w_v2   = (const float*)d_in[18];
    const float* w_s2   = (const float*)d_in[19];
    const float* beta2  = (const float*)d_in[20];
    const float* aw2    = (const float*)d_in[21];
    const float* theta2 = (const float*)d_in[22];
    float* out = (float*)d_out;

    k_zero<<<1024, 256>>>();
    k_scalars<<<1, 1>>>(beta1, aw1, theta1, beta2, aw2, theta2);
    k_indeg<<<(EE + 255) / 256, 256>>>(dst);
    k_scan<<<1, 1024>>>();
    k_scatter<<<(EE + 255) / 256, 256>>>(dst);
    k_dense16<<<(NN * NC + 255) / 256, 256>>>(latp, sl_w, sl_b, (size_t)0, HLATP_OFF);
    k_dense16<<<(NN * NC + 255) / 256, 256>>>(nullptr, slo_w, slo_b, HLATP_OFF, HLATP2_OFF);
    k_gemm1<<<(NN + 127) / 128, 256>>>(x, fc1_w);
    k_node1<<<(NN * 32 + 255) / 256, 256>>>(w_u1, w_v1);
    k_edge1<<<(EE * 32 + 255) / 256, 256>>>(src, dst, w_s1);
    k_agg1<<<(NN * 32 + 255) / 256, 256>>>(src);
    k_gemm2<<<(NN * NC + 255) / 256, 256>>>(fc2_w);
    k_node2<<<(NN + 255) / 256, 256>>>(w_u2, w_v2);
    k_edge2<<<(EE + 255) / 256, 256>>>(src, dst, w_s2);
    k_loss<<<(EE + 255) / 256, 256>>>(src, dst, weights);
    k_agg2_final<<<(NN * 32 + 255) / 256, 256>>>(src, out, out_size);
}

// round 3
// speedup vs baseline: 1.4730x; 1.1235x over previous
#include <cuda_runtime.h>
#include <math.h>

#define NN 50000
#define EE 800000
#define NF 512
#define NH 128
#define NC 16
#define NEG 0.2f
#define FEPS 1e-9f
#define NBLK ((NN + 255) / 256)

// ---------------- scratch layout (floats) ----------------
// zeroed-every-launch region first (contiguous):
#define INDEG_OFF ((size_t)0)
#define OUTW1_OFF (INDEG_OFF + NN)
#define INW1_OFF  (OUTW1_OFF + NN)
#define OUTW2_OFF (INW1_OFF + NN)
#define INW2_OFF  (OUTW2_OFF + NN)
#define CUR_OFF   (INW2_OFF + NN)          // int cursor per node
#define LOSS_OFF  (CUR_OFF + NN)
#define ZERO_TOTAL (LOSS_OFF + 1)
// non-zeroed region:
#define HLATP_OFF  (((ZERO_TOTAL + 3)/4)*4)
#define HLATP2_OFF (HLATP_OFF + (size_t)NN*NC)
#define H1_OFF     (HLATP2_OFF + (size_t)NN*NC)
#define H2_OFF     (H1_OFF + (size_t)NN*NH)
#define RST1_OFF   (H2_OFF + (size_t)NN*NC)
#define EL1_OFF    (RST1_OFF + (size_t)NN*NH)
#define ER1_OFF    (EL1_OFF + NN)
#define EL2_OFF    (ER1_OFF + NN)
#define ER2_OFF    (EL2_OFF + NN)
#define EW_OFF     (ER2_OFF + NN)
#define RP_OFF     (EW_OFF + EE)           // int row_ptr[NN+1]
#define EIDX_OFF   (((RP_OFF + NN + 1 + 3)/4)*4)  // int eidx[EE]
#define SC_OFF     (EIDX_OFF + EE)
#define PART_OFF   (SC_OFF + 16)           // int partials[NBLK]
#define TOTALF     (PART_OFF + NBLK + 16)

__device__ __align__(256) float g_s[TOTALF];

__device__ __forceinline__ float elu1(float x){ return x > 0.f ? x : expf(x) - 1.f; }

// ---------------- zero + scalars ----------------
__global__ void k_zero(const float* b1, const float* a1, const float* t1,
                       const float* b2, const float* a2, const float* t2){
    if (blockIdx.x == 0 && threadIdx.x == 0){
        float* sc = g_s + SC_OFF;
        sc[0] = 2.0f / (expf(-b1[0]) + 1.0f);
        float e0 = expf(a1[0]), e1 = expf(a1[1]);
        sc[1] = e0 / (e0 + e1); sc[2] = e1 / (e0 + e1);
        sc[3] = FEPS / (expf(-t1[0]) + 1.0f);
        sc[4] = 2.0f / (expf(-b2[0]) + 1.0f);
        float f0 = expf(a2[0]), f1 = expf(a2[1]);
        sc[5] = f0 / (f0 + f1); sc[6] = f1 / (f0 + f1);
        sc[7] = FEPS / (expf(-t2[0]) + 1.0f);
    }
    size_t i = (size_t)blockIdx.x * blockDim.x + threadIdx.x;
    size_t stride = (size_t)gridDim.x * blockDim.x;
    for (; i < ZERO_TOTAL; i += stride) g_s[i] = 0.f;
}

__global__ void k_indeg(const int* __restrict__ dst){
    int e = blockIdx.x * blockDim.x + threadIdx.x;
    if (e < EE) atomicAdd(&g_s[INDEG_OFF + dst[e]], 1.0f);
}

// ---------------- multi-block scan: per-block inclusive scan ----------------
__global__ void k_scanA(){
    __shared__ int wsum[8];
    int lane = threadIdx.x & 31, wid = threadIdx.x >> 5;
    int i = blockIdx.x * 256 + threadIdx.x;
    int v = (i < NN) ? (int)g_s[INDEG_OFF + i] : 0;
    int x = v;
#pragma unroll
    for (int o = 1; o < 32; o <<= 1){
        int t = __shfl_up_sync(0xffffffffu, x, o);
        if (lane >= o) x += t;
    }
    if (lane == 31) wsum[wid] = x;
    __syncthreads();
    if (threadIdx.x < 8){
        int y = wsum[threadIdx.x];
#pragma unroll
        for (int o = 1; o < 8; o <<= 1){
            int t = __shfl_up_sync(0xffu, y, o);
            if (threadIdx.x >= o) y += t;
        }
        wsum[threadIdx.x] = y;
    }
    __syncthreads();
    int incl = x + (wid ? wsum[wid - 1] : 0);
    if (i < NN) ((int*)(g_s + RP_OFF))[i + 1] = incl;
    if (threadIdx.x == 255) ((int*)(g_s + PART_OFF))[blockIdx.x] = incl;
}

// add preceding-block offsets
__global__ void k_scanB(){
    __shared__ int off_s;
    if (threadIdx.x == 0) off_s = 0;
    __syncthreads();
    const int* part = (const int*)(g_s + PART_OFF);
    int p = 0;
    for (int j = threadIdx.x; j < blockIdx.x; j += 256) p += part[j];
#pragma unroll
    for (int o = 16; o; o >>= 1) p += __shfl_xor_sync(0xffffffffu, p, o);
    if ((threadIdx.x & 31) == 0 && p) atomicAdd(&off_s, p);
    __syncthreads();
    int i = blockIdx.x * 256 + threadIdx.x;
    if (i < NN) ((int*)(g_s + RP_OFF))[i + 1] += off_s;
    if (blockIdx.x == 0 && threadIdx.x == 0) ((int*)(g_s + RP_OFF))[0] = 0;
}

__global__ void k_scatter(const int* __restrict__ dst){
    int e = blockIdx.x * blockDim.x + threadIdx.x;
    if (e >= EE) return;
    int d = dst[e];
    int* cur = (int*)(g_s + CUR_OFF);
    const int* rp = (const int*)(g_s + RP_OFF);
    int p = rp[d] + atomicAdd(&cur[d], 1);
    ((int*)(g_s + EIDX_OFF))[p] = e;
}

// ---------------- fused double 16x16 dense: hlatp + hlatp2 ----------------
__global__ void k_dense2x(const float* __restrict__ latp,
                          const float* __restrict__ W1, const float* __restrict__ B1,
                          const float* __restrict__ W2, const float* __restrict__ B2){
    __shared__ float W1s[256], W2s[256], bb1[16], bb2[16];
    int t = threadIdx.x;
    W1s[t] = W1[t]; W2s[t] = W2[t];
    if (t < 16){ bb1[t] = B1[t]; bb2[t] = B2[t]; }
    __syncthreads();
    int idx = blockIdx.x * blockDim.x + t;
    if (idx >= NN * NC) return;
    int c = idx & 15;
    float in = latp[idx];
    float acc = bb1[c];
#pragma unroll
    for (int k = 0; k < 16; k++){
        float ik = __shfl_sync(0xffffffffu, in, k, 16);
        acc = fmaf(ik, W1s[k * 16 + c], acc);
    }
    float h = elu1(acc);
    g_s[HLATP_OFF + idx] = h;
    float acc2 = bb2[c];
#pragma unroll
    for (int k = 0; k < 16; k++){
        float hk = __shfl_sync(0xffffffffu, h, k, 16);
        acc2 = fmaf(hk, W2s[k * 16 + c], acc2);
    }
    g_s[HLATP2_OFF + idx] = elu1(acc2);
}

// ---------------- GEMM1: h1 = x (NNxNF) @ fc1_w (NFxNH) ----------------
__global__ __launch_bounds__(256) void k_gemm1(const float* __restrict__ A,
                                               const float* __restrict__ B){
    __shared__ float As[16][132];
    __shared__ float Bs[16][128];
    int tid = threadIdx.x;
    int m0 = blockIdx.x * 128;
    int tx = tid & 15, ty = tid >> 4;
    float acc[8][8];
#pragma unroll
    for (int i = 0; i < 8; i++)
#pragma unroll
        for (int j = 0; j < 8; j++) acc[i][j] = 0.f;

    for (int k0 = 0; k0 < NF; k0 += 16){
#pragma unroll
        for (int l = 0; l < 2; l++){
            int id = tid + l * 256;
            int row = id >> 2, kc = (id & 3) * 4;
            int gm = m0 + row; if (gm >= NN) gm = NN - 1;
            float4 v = *(const float4*)(A + (size_t)gm * NF + k0 + kc);
            As[kc + 0][row] = v.x; As[kc + 1][row] = v.y;
            As[kc + 2][row] = v.z; As[kc + 3][row] = v.w;
        }
#pragma unroll
        for (int l = 0; l < 2; l++){
            int id = tid + l * 256;
            int row = id >> 5, c = (id & 31) * 4;
            float4 v = *(const float4*)(B + (size_t)(k0 + row) * NH + c);
            *(float4*)&Bs[row][c] = v;
        }
        __syncthreads();
#pragma unroll
        for (int kk = 0; kk < 16; kk++){
            float a[8], b[8];
            *(float4*)(a)     = *(float4*)&As[kk][ty * 8];
            *(float4*)(a + 4) = *(float4*)&As[kk][ty * 8 + 4];
            *(float4*)(b)     = *(float4*)&Bs[kk][tx * 8];
            *(float4*)(b + 4) = *(float4*)&Bs[kk][tx * 8 + 4];
#pragma unroll
            for (int i = 0; i < 8; i++)
#pragma unroll
                for (int j = 0; j < 8; j++) acc[i][j] = fmaf(a[i], b[j], acc[i][j]);
        }
        __syncthreads();
    }
#pragma unroll
    for (int i = 0; i < 8; i++){
        int gm = m0 + ty * 8 + i;
        if (gm < NN){
            float* c = g_s + H1_OFF + (size_t)gm * NH + tx * 8;
            *(float4*)c       = make_float4(acc[i][0], acc[i][1], acc[i][2], acc[i][3]);
            *(float4*)(c + 4) = make_float4(acc[i][4], acc[i][5], acc[i][6], acc[i][7]);
        }
    }
}

// ---------------- per-node scalars layer1 (el, er) ----------------
__global__ void k_node1(const float* __restrict__ wu, const float* __restrict__ wv){
    int warp = (blockIdx.x * blockDim.x + threadIdx.x) >> 5;
    int lane = threadIdx.x & 31;
    if (warp >= NN) return;
    const float4* h = (const float4*)(g_s + H1_OFF + (size_t)warp * NH);
    float4 hv = h[lane];
    float4 u4 = ((const float4*)wu)[lane];
    float4 v4 = ((const float4*)wv)[lane];
    float l0 = hv.x > 0.f ? hv.x : NEG * hv.x;
    float l1 = hv.y > 0.f ? hv.y : NEG * hv.y;
    float l2 = hv.z > 0.f ? hv.z : NEG * hv.z;
    float l3 = hv.w > 0.f ? hv.w : NEG * hv.w;
    float u = l0 * u4.x + l1 * u4.y + l2 * u4.z + l3 * u4.w;
    float v = l0 * v4.x + l1 * v4.y + l2 * v4.z + l3 * v4.w;
#pragma unroll
    for (int o = 16; o; o >>= 1){
        u += __shfl_xor_sync(0xffffffffu, u, o);
        v += __shfl_xor_sync(0xffffffffu, v, o);
    }
    if (!lane){ g_s[EL1_OFF + warp] = u; g_s[ER1_OFF + warp] = v; }
}

// ---------------- edge pass 1: compute ew, accumulate outw/inw ----------------
__global__ void k_edge1(const int* __restrict__ src, const int* __restrict__ dst,
                        const float* __restrict__ ws){
    int e = (blockIdx.x * blockDim.x + threadIdx.x) >> 5;
    int lane = threadIdx.x & 31;
    if (e >= EE) return;
    int s = src[e], d = dst[e];
    float4 a = ((const float4*)(g_s + H1_OFF + (size_t)s * NH))[lane];
    float4 b = ((const float4*)(g_s + H1_OFF + (size_t)d * NH))[lane];
    float q, sdf;
    q = a.x - b.x; sdf  = q * q;
    q = a.y - b.y; sdf += q * q;
    q = a.z - b.z; sdf += q * q;
    q = a.w - b.w; sdf += q * q;
    float sds = 0.f, st = 0.f;
    if (lane < NC){
        float fs = g_s[HLATP_OFF + (size_t)s * NC + lane];
        float fd = g_s[HLATP_OFF + (size_t)d * NC + lane];
        float df = fs - fd; sds = df * df;
        st = fs * ws[lane] * fd;
    }
#pragma unroll
    for (int o = 16; o; o >>= 1){
        sdf += __shfl_xor_sync(0xffffffffu, sdf, o);
        sds += __shfl_xor_sync(0xffffffffu, sds, o);
        st  += __shfl_xor_sync(0xffffffffu, st,  o);
    }
    if (!lane){
        const float* sc = g_s + SC_OFF;
        float ev = g_s[EL1_OFF + s] + g_s[ER1_OFF + d] + st;
        float dd = sc[1] * sdf + sc[2] * sds;
        float ew = expf(ev - sc[0] * dd) + FEPS;
        g_s[EW_OFF + e] = ew;
        atomicAdd(&g_s[OUTW1_OFF + s], ew);
        atomicAdd(&g_s[INW1_OFF + d], ew);
    }
}

// ---------------- CSR aggregation layer1 (fused with perm-residual + elu) ----------------
__global__ void k_agg1(const int* __restrict__ src){
    int d = (blockIdx.x * blockDim.x + threadIdx.x) >> 5;
    int lane = threadIdx.x & 31;
    if (d >= NN) return;
    const int* rp = (const int*)(g_s + RP_OFF);
    const int* eidx = (const int*)(g_s + EIDX_OFF);
    int b = rp[d], eend = rp[d + 1];
    float inw_r = rsqrtf(g_s[INW1_OFF + d]);
    float ax = 0.f, ay = 0.f, az = 0.f, aw = 0.f;
    float bx = 0.f, by = 0.f, bz = 0.f, bw = 0.f;
    int j = b;
    for (; j + 1 < eend; j += 2){
        int e0 = eidx[j], e1 = eidx[j + 1];
        int s0 = src[e0], s1 = src[e1];
        float a0 = inw_r * rsqrtf(g_s[OUTW1_OFF + s0]) * g_s[EW_OFF + e0];
        float a1 = inw_r * rsqrtf(g_s[OUTW1_OFF + s1]) * g_s[EW_OFF + e1];
        float4 h0 = ((const float4*)(g_s + H1_OFF + (size_t)s0 * NH))[lane];
        float4 h1 = ((const float4*)(g_s + H1_OFF + (size_t)s1 * NH))[lane];
        ax = fmaf(h0.x, a0, ax); ay = fmaf(h0.y, a0, ay);
        az = fmaf(h0.z, a0, az); aw = fmaf(h0.w, a0, aw);
        bx = fmaf(h1.x, a1, bx); by = fmaf(h1.y, a1, by);
        bz = fmaf(h1.z, a1, bz); bw = fmaf(h1.w, a1, bw);
    }
    if (j < eend){
        int e0 = eidx[j];
        int s0 = src[e0];
        float a0 = inw_r * rsqrtf(g_s[OUTW1_OFF + s0]) * g_s[EW_OFF + e0];
        float4 h0 = ((const float4*)(g_s + H1_OFF + (size_t)s0 * NH))[lane];
        ax = fmaf(h0.x, a0, ax); ay = fmaf(h0.y, a0, ay);
        az = fmaf(h0.z, a0, az); aw = fmaf(h0.w, a0, aw);
    }
    float perm = g_s[SC_OFF + 3] / (g_s[INDEG_OFF + d] + FEPS);
    float4 hd = ((const float4*)(g_s + H1_OFF + (size_t)d * NH))[lane];
    float4 r;
    r.x = elu1(ax + bx + hd.x * perm);
    r.y = elu1(ay + by + hd.y * perm);
    r.z = elu1(az + bz + hd.z * perm);
    r.w = elu1(aw + bw + hd.w * perm);
    ((float4*)(g_s + RST1_OFF + (size_t)d * NH))[lane] = r;
}

// ---------------- GEMM2: h2 = rst1 (NNxNH) @ fc2_w (NHxNC) ----------------
__global__ void k_gemm2(const float* __restrict__ W){
    __shared__ float Ws[NH * NC];
    for (int i = threadIdx.x; i < NH * NC; i += blockDim.x) Ws[i] = W[i];
    __syncthreads();
    int idx = blockIdx.x * blockDim.x + threadIdx.x;
    if (idx >= NN * NC) return;
    int n = idx >> 4, c = idx & 15;
    const float* h = g_s + RST1_OFF + (size_t)n * NH;
    float acc = 0.f;
#pragma unroll
    for (int k = 0; k < NH; k++) acc = fmaf(h[k], Ws[k * NC + c], acc);
    g_s[H2_OFF + idx] = acc;
}

// ---------------- per-node scalars layer2 ----------------
__global__ void k_node2(const float* __restrict__ wu, const float* __restrict__ wv){
    int n = blockIdx.x * blockDim.x + threadIdx.x;
    if (n >= NN) return;
    const float4* h = (const float4*)(g_s + H2_OFF + (size_t)n * NC);
    const float4* u4 = (const float4*)wu;
    const float4* v4 = (const float4*)wv;
    float u = 0.f, v = 0.f;
#pragma unroll
    for (int j = 0; j < 4; j++){
        float4 a = h[j], uu = u4[j], vv = v4[j];
        float l0 = a.x > 0.f ? a.x : NEG * a.x;
        float l1 = a.y > 0.f ? a.y : NEG * a.y;
        float l2 = a.z > 0.f ? a.z : NEG * a.z;
        float l3 = a.w > 0.f ? a.w : NEG * a.w;
        u += l0 * uu.x + l1 * uu.y + l2 * uu.z + l3 * uu.w;
        v += l0 * vv.x + l1 * vv.y + l2 * vv.z + l3 * vv.w;
    }
    g_s[EL2_OFF + n] = u;
    g_s[ER2_OFF + n] = v;
}

// ---------------- edge pass 2 (+ position loss fused) ----------------
__global__ void k_edge2(const int* __restrict__ src, const int* __restrict__ dst,
                        const float* __restrict__ ws, const float* __restrict__ lw){
    int e = blockIdx.x * blockDim.x + threadIdx.x;
    float lacc = 0.f;
    if (e < EE){
        int s = src[e], d = dst[e];
        const float4* hs = (const float4*)(g_s + H2_OFF + (size_t)s * NC);
        const float4* hd = (const float4*)(g_s + H2_OFF + (size_t)d * NC);
        const float4* fs = (const float4*)(g_s + HLATP2_OFF + (size_t)s * NC);
        const float4* fd = (const float4*)(g_s + HLATP2_OFF + (size_t)d * NC);
        const float4* w4 = (const float4*)ws;
        float sdf = 0.f, sds = 0.f, st = 0.f, pdot = 0.f;
#pragma unroll
        for (int j = 0; j < 4; j++){
            float4 a = hs[j], b = hd[j];
            float q;
            q = a.x - b.x; sdf += q * q;
            q = a.y - b.y; sdf += q * q;
            q = a.z - b.z; sdf += q * q;
            q = a.w - b.w; sdf += q * q;
            float4 p = fs[j], r = fd[j], w = w4[j];
            q = p.x - r.x; sds += q * q;
            q = p.y - r.y; sds += q * q;
            q = p.z - r.z; sds += q * q;
            q = p.w - r.w; sds += q * q;
            st += p.x * w.x * r.x + p.y * w.y * r.y + p.z * w.z * r.z + p.w * w.w * r.w;
            pdot += p.x * r.x + p.y * r.y + p.z * r.z + p.w * r.w;
        }
        const float* sc = g_s + SC_OFF;
        float ev = g_s[EL2_OFF + s] + g_s[ER2_OFF + d] + st;
        float ew = expf(ev - sc[4] * (sc[5] * sdf + sc[6] * sds)) + FEPS;
        g_s[EW_OFF + e] = ew;
        atomicAdd(&g_s[OUTW2_OFF + s], ew);
        atomicAdd(&g_s[INW2_OFF + d], ew);
        lacc = lw[e] * pdot;
    }
#pragma unroll
    for (int o = 16; o; o >>= 1) lacc += __shfl_xor_sync(0xffffffffu, lacc, o);
    if ((threadIdx.x & 31) == 0) atomicAdd(&g_s[LOSS_OFF], lacc);
}

// ---------------- CSR aggregation layer2 fused with final log-softmax ----------------
__global__ void k_agg2_final(const int* __restrict__ src, float* __restrict__ out,
                             int out_size){
    int d = (blockIdx.x * blockDim.x + threadIdx.x) >> 5;
    int lane = threadIdx.x & 31;
    if (d >= NN) return;
    if (d == 0 && lane == 0 && out_size > NN * NC) out[NN * NC] = g_s[LOSS_OFF];
    const int* rp = (const int*)(g_s + RP_OFF);
    const int* eidx = (const int*)(g_s + EIDX_OFF);
    int b = rp[d], eend = rp[d + 1];
    int c = lane & 15;
    int half = lane >> 4;           // two half-warps process even/odd edges
    float inw_r = rsqrtf(g_s[INW2_OFF + d]);
    float acc = 0.f;
    for (int j = b + half; j < eend; j += 2){
        int e = eidx[j];
        int s = src[e];
        float a = inw_r * rsqrtf(g_s[OUTW2_OFF + s]) * g_s[EW_OFF + e];
        acc = fmaf(g_s[H2_OFF + (size_t)s * NC + c], a, acc);
    }
    acc += __shfl_xor_sync(0xffffffffu, acc, 16);
    float perm = g_s[SC_OFF + 7] / (g_s[INDEG_OFF + d] + FEPS);
    float t = elu1(acc + g_s[H2_OFF + (size_t)d * NC + c] * perm);
    float mx = t;
#pragma unroll
    for (int o = 8; o; o >>= 1) mx = fmaxf(mx, __shfl_xor_sync(0xffffffffu, mx, o));
    float s2 = expf(t - mx);
#pragma unroll
    for (int o = 8; o; o >>= 1) s2 += __shfl_xor_sync(0xffffffffu, s2, o);
    float lse = mx + logf(s2);
    if (lane < 16) out[(size_t)d * NC + c] = t - lse;
}

// ---------------- launch ----------------
extern "C" void kernel_launch(void* const* d_in, const int* in_sizes, int n_in,
                              void* d_out, int out_size){
    const int*   src    = (const int*)  d_in[0];
    const int*   dst    = (const int*)  d_in[1];
    const float* x      = (const float*)d_in[2];
    const float* weights= (const float*)d_in[3];
    const float* latp   = (const float*)d_in[4];
    const float* sl_w   = (const float*)d_in[5];
    const float* sl_b   = (const float*)d_in[6];
    const float* slo_w  = (const float*)d_in[7];
    const float* slo_b  = (const float*)d_in[8];
    const float* fc1_w  = (const float*)d_in[9];
    const float* w_u1   = (const float*)d_in[10];
    const float* w_v1   = (const float*)d_in[11];
    const float* w_s1   = (const float*)d_in[12];
    const float* beta1  = (const float*)d_in[13];
    const float* aw1    = (const float*)d_in[14];
    const float* theta1 = (const float*)d_in[15];
    const float* fc2_w  = (const float*)d_in[16];
    const float* w_u2   = (const float*)d_in[17];
    const float* w_v2   = (const float*)d_in[18];
    const float* w_s2   = (const float*)d_in[19];
    const float* beta2  = (const float*)d_in[20];
    const float* aw2    = (const float*)d_in[21];
    const float* theta2 = (const float*)d_in[22];
    float* out = (float*)d_out;

    k_zero<<<1024, 256>>>(beta1, aw1, theta1, beta2, aw2, theta2);
    k_indeg<<<(EE + 255) / 256, 256>>>(dst);
    k_scanA<<<NBLK, 256>>>();
    k_scanB<<<NBLK, 256>>>();
    k_scatter<<<(EE + 255) / 256, 256>>>(dst);
    k_dense2x<<<(NN * NC + 255) / 256, 256>>>(latp, sl_w, sl_b, slo_w, slo_b);
    k_gemm1<<<(NN + 127) / 128, 256>>>(x, fc1_w);
    k_node1<<<(NN * 32 + 255) / 256, 256>>>(w_u1, w_v1);
    k_edge1<<<(EE * 32 + 255) / 256, 256>>>(src, dst, w_s1);
    k_agg1<<<(NN * 32 + 255) / 256, 256>>>(src);
    k_gemm2<<<(NN * NC + 255) / 256, 256>>>(fc2_w);
    k_node2<<<(NN + 255) / 256, 256>>>(w_u2, w_v2);
    k_edge2<<<(EE + 255) / 256, 256>>>(src, dst, w_s2, weights);
    k_agg2_final<<<(NN * 32 + 255) / 256, 256>>>(src, out, out_size);
}

// round 4
// speedup vs baseline: 1.8076x; 1.2271x over previous
#include <cuda_runtime.h>
#include <math.h>

#define NN 50000
#define EE 800000
#define NF 512
#define NH 128
#define NC 16
#define NEG 0.2f
#define FEPS 1e-9f
#define NBLK ((NN + 255) / 256)

// ---------------- scratch layout (floats) ----------------
#define OUTW1_OFF ((size_t)0)
#define INW1_OFF  (OUTW1_OFF + NN)
#define OUTW2_OFF (INW1_OFF + NN)
#define INW2_OFF  (OUTW2_OFF + NN)
#define CUR_OFF   (INW2_OFF + NN)          // int cursors
#define DEG_OFF   (CUR_OFF + NN)           // int in-degree
#define LOSS_OFF  (DEG_OFF + NN)
#define ZERO_TOTAL (LOSS_OFF + 1)
// non-zeroed region:
#define HLATP_OFF  (((ZERO_TOTAL + 3)/4)*4)
#define HLATP2_OFF (HLATP_OFF + (size_t)NN*NC)
#define H1_OFF     (HLATP2_OFF + (size_t)NN*NC)
#define H2_OFF     (H1_OFF + (size_t)NN*NH)
#define RST1_OFF   (H2_OFF + (size_t)NN*NC)
#define EL1_OFF    (RST1_OFF + (size_t)NN*NH)
#define ER1_OFF    (EL1_OFF + NN)
#define EL2_OFF    (ER1_OFF + NN)
#define ER2_OFF    (EL2_OFF + NN)
#define EW_OFF     (ER2_OFF + NN)          // edge weights in CSR order
#define RP_OFF     (EW_OFF + EE)           // int row_ptr[NN+1]
#define CSRC_OFF   (((RP_OFF + NN + 1 + 3)/4)*4)  // int csr_src[EE]
#define POS_OFF    (CSRC_OFF + EE)         // int pos[EE]: edge -> csr slot
#define SC_OFF     (POS_OFF + EE)
#define PART_OFF   (SC_OFF + 16)
#define TOTALF     (PART_OFF + NBLK + 16)

__device__ __align__(256) float g_s[TOTALF];

__device__ __forceinline__ float elu1(float x){ return x > 0.f ? x : expf(x) - 1.f; }

// ---------------- zero + scalars ----------------
__global__ void k_zero(const float* b1, const float* a1, const float* t1,
                       const float* b2, const float* a2, const float* t2){
    if (blockIdx.x == 0 && threadIdx.x == 0){
        float* sc = g_s + SC_OFF;
        sc[0] = 2.0f / (expf(-b1[0]) + 1.0f);
        float e0 = expf(a1[0]), e1 = expf(a1[1]);
        sc[1] = e0 / (e0 + e1); sc[2] = e1 / (e0 + e1);
        sc[3] = FEPS / (expf(-t1[0]) + 1.0f);
        sc[4] = 2.0f / (expf(-b2[0]) + 1.0f);
        float f0 = expf(a2[0]), f1 = expf(a2[1]);
        sc[5] = f0 / (f0 + f1); sc[6] = f1 / (f0 + f1);
        sc[7] = FEPS / (expf(-t2[0]) + 1.0f);
    }
    size_t i = (size_t)blockIdx.x * blockDim.x + threadIdx.x;
    size_t stride = (size_t)gridDim.x * blockDim.x;
    for (; i < ZERO_TOTAL; i += stride) g_s[i] = 0.f;
}

__global__ void k_indeg(const int* __restrict__ dst){
    int e = blockIdx.x * blockDim.x + threadIdx.x;
    if (e < EE) atomicAdd((int*)(g_s + DEG_OFF) + dst[e], 1);
}

// ---------------- multi-block scan ----------------
__global__ void k_scanA(){
    __shared__ int wsum[8];
    int lane = threadIdx.x & 31, wid = threadIdx.x >> 5;
    int i = blockIdx.x * 256 + threadIdx.x;
    int v = (i < NN) ? ((const int*)(g_s + DEG_OFF))[i] : 0;
    int x = v;
#pragma unroll
    for (int o = 1; o < 32; o <<= 1){
        int t = __shfl_up_sync(0xffffffffu, x, o);
        if (lane >= o) x += t;
    }
    if (lane == 31) wsum[wid] = x;
    __syncthreads();
    if (threadIdx.x < 8){
        int y = wsum[threadIdx.x];
#pragma unroll
        for (int o = 1; o < 8; o <<= 1){
            int t = __shfl_up_sync(0xffu, y, o);
            if (threadIdx.x >= o) y += t;
        }
        wsum[threadIdx.x] = y;
    }
    __syncthreads();
    int incl = x + (wid ? wsum[wid - 1] : 0);
    if (i < NN) ((int*)(g_s + RP_OFF))[i + 1] = incl;
    if (threadIdx.x == 255) ((int*)(g_s + PART_OFF))[blockIdx.x] = incl;
}

__global__ void k_scanB(){
    __shared__ int off_s;
    if (threadIdx.x == 0) off_s = 0;
    __syncthreads();
    const int* part = (const int*)(g_s + PART_OFF);
    int p = 0;
    for (int j = threadIdx.x; j < blockIdx.x; j += 256) p += part[j];
#pragma unroll
    for (int o = 16; o; o >>= 1) p += __shfl_xor_sync(0xffffffffu, p, o);
    if ((threadIdx.x & 31) == 0 && p) atomicAdd(&off_s, p);
    __syncthreads();
    int i = blockIdx.x * 256 + threadIdx.x;
    if (i < NN) ((int*)(g_s + RP_OFF))[i + 1] += off_s;
    if (blockIdx.x == 0 && threadIdx.x == 0) ((int*)(g_s + RP_OFF))[0] = 0;
}

__global__ void k_scatter(const int* __restrict__ src, const int* __restrict__ dst){
    int e = blockIdx.x * blockDim.x + threadIdx.x;
    if (e >= EE) return;
    int d = dst[e];
    int* cur = (int*)(g_s + CUR_OFF);
    const int* rp = (const int*)(g_s + RP_OFF);
    int p = rp[d] + atomicAdd(&cur[d], 1);
    ((int*)(g_s + CSRC_OFF))[p] = src[e];
    ((int*)(g_s + POS_OFF))[e] = p;
}

// ---------------- fused double 16x16 dense ----------------
__global__ void k_dense2x(const float* __restrict__ latp,
                          const float* __restrict__ W1, const float* __restrict__ B1,
                          const float* __restrict__ W2, const float* __restrict__ B2){
    __shared__ float W1s[256], W2s[256], bb1[16], bb2[16];
    int t = threadIdx.x;
    W1s[t] = W1[t]; W2s[t] = W2[t];
    if (t < 16){ bb1[t] = B1[t]; bb2[t] = B2[t]; }
    __syncthreads();
    int idx = blockIdx.x * blockDim.x + t;
    if (idx >= NN * NC) return;
    int c = idx & 15;
    float in = latp[idx];
    float acc = bb1[c];
#pragma unroll
    for (int k = 0; k < 16; k++){
        float ik = __shfl_sync(0xffffffffu, in, k, 16);
        acc = fmaf(ik, W1s[k * 16 + c], acc);
    }
    float h = elu1(acc);
    g_s[HLATP_OFF + idx] = h;
    float acc2 = bb2[c];
#pragma unroll
    for (int k = 0; k < 16; k++){
        float hk = __shfl_sync(0xffffffffu, h, k, 16);
        acc2 = fmaf(hk, W2s[k * 16 + c], acc2);
    }
    g_s[HLATP2_OFF + idx] = elu1(acc2);
}

// ---------------- GEMM1 (K-tile 32) + fused el1/er1 epilogue ----------------
__global__ __launch_bounds__(256) void k_gemm1(const float* __restrict__ A,
                                               const float* __restrict__ B,
                                               const float* __restrict__ wu,
                                               const float* __restrict__ wv){
    __shared__ float As[32][132];
    __shared__ float Bs[32][128];
    int tid = threadIdx.x;
    int m0 = blockIdx.x * 128;
    int tx = tid & 15, ty = tid >> 4;
    float acc[8][8];
#pragma unroll
    for (int i = 0; i < 8; i++)
#pragma unroll
        for (int j = 0; j < 8; j++) acc[i][j] = 0.f;

    for (int k0 = 0; k0 < NF; k0 += 32){
#pragma unroll
        for (int l = 0; l < 4; l++){
            int id = tid + l * 256;
            int row = id >> 3, kc = (id & 7) * 4;
            int gm = m0 + row; if (gm >= NN) gm = NN - 1;
            float4 v = *(const float4*)(A + (size_t)gm * NF + k0 + kc);
            As[kc + 0][row] = v.x; As[kc + 1][row] = v.y;
            As[kc + 2][row] = v.z; As[kc + 3][row] = v.w;
        }
#pragma unroll
        for (int l = 0; l < 4; l++){
            int id = tid + l * 256;
            int row = id >> 5, c = (id & 31) * 4;
            float4 v = *(const float4*)(B + (size_t)(k0 + row) * NH + c);
            *(float4*)&Bs[row][c] = v;
        }
        __syncthreads();
#pragma unroll
        for (int kk = 0; kk < 32; kk++){
            float a[8], b[8];
            *(float4*)(a)     = *(float4*)&As[kk][ty * 8];
            *(float4*)(a + 4) = *(float4*)&As[kk][ty * 8 + 4];
            *(float4*)(b)     = *(float4*)&Bs[kk][tx * 8];
            *(float4*)(b + 4) = *(float4*)&Bs[kk][tx * 8 + 4];
#pragma unroll
            for (int i = 0; i < 8; i++)
#pragma unroll
                for (int j = 0; j < 8; j++) acc[i][j] = fmaf(a[i], b[j], acc[i][j]);
        }
        __syncthreads();
    }
    float wuv[8], wvv[8];
    *(float4*)(wuv)     = ((const float4*)wu)[tx * 2];
    *(float4*)(wuv + 4) = ((const float4*)wu)[tx * 2 + 1];
    *(float4*)(wvv)     = ((const float4*)wv)[tx * 2];
    *(float4*)(wvv + 4) = ((const float4*)wv)[tx * 2 + 1];
#pragma unroll
    for (int i = 0; i < 8; i++){
        int gm = m0 + ty * 8 + i;
        float ep = 0.f, vp = 0.f;
#pragma unroll
        for (int j = 0; j < 8; j++){
            float cv = acc[i][j];
            float l = cv > 0.f ? cv : NEG * cv;
            ep = fmaf(l, wuv[j], ep);
            vp = fmaf(l, wvv[j], vp);
        }
#pragma unroll
        for (int o = 1; o < 16; o <<= 1){
            ep += __shfl_xor_sync(0xffffffffu, ep, o);
            vp += __shfl_xor_sync(0xffffffffu, vp, o);
        }
        if (gm < NN){
            float* c = g_s + H1_OFF + (size_t)gm * NH + tx * 8;
            *(float4*)c       = make_float4(acc[i][0], acc[i][1], acc[i][2], acc[i][3]);
            *(float4*)(c + 4) = make_float4(acc[i][4], acc[i][5], acc[i][6], acc[i][7]);
            if (tx == 0){ g_s[EL1_OFF + gm] = ep; g_s[ER1_OFF + gm] = vp; }
        }
    }
}

// ---------------- edge pass 1: 8 lanes per edge ----------------
__global__ void k_edge1(const int* __restrict__ src, const int* __restrict__ dst,
                        const float* __restrict__ ws){
    int t = blockIdx.x * blockDim.x + threadIdx.x;
    int e = t >> 3, l = t & 7;
    if (e >= EE) return;
    int s = src[e], d = dst[e];
    const float4* hs = (const float4*)(g_s + H1_OFF + (size_t)s * NH);
    const float4* hd = (const float4*)(g_s + H1_OFF + (size_t)d * NH);
    float sdf = 0.f;
#pragma unroll
    for (int j = 0; j < 4; j++){
        float4 a = hs[l + 8 * j];
        float4 b = hd[l + 8 * j];
        float q;
        q = a.x - b.x; sdf = fmaf(q, q, sdf);
        q = a.y - b.y; sdf = fmaf(q, q, sdf);
        q = a.z - b.z; sdf = fmaf(q, q, sdf);
        q = a.w - b.w; sdf = fmaf(q, q, sdf);
    }
    float2 fs = *(const float2*)(g_s + HLATP_OFF + (size_t)s * NC + l * 2);
    float2 fd = *(const float2*)(g_s + HLATP_OFF + (size_t)d * NC + l * 2);
    float2 w2 = *(const float2*)(ws + l * 2);
    float q0 = fs.x - fd.x, q1 = fs.y - fd.y;
    float sds = q0 * q0 + q1 * q1;
    float st = fs.x * w2.x * fd.x + fs.y * w2.y * fd.y;
#pragma unroll
    for (int o = 4; o; o >>= 1){
        sdf += __shfl_xor_sync(0xffffffffu, sdf, o);
        sds += __shfl_xor_sync(0xffffffffu, sds, o);
        st  += __shfl_xor_sync(0xffffffffu, st,  o);
    }
    if (l == 0){
        const float* sc = g_s + SC_OFF;
        float ev = g_s[EL1_OFF + s] + g_s[ER1_OFF + d] + st;
        float dd = sc[1] * sdf + sc[2] * sds;
        float ew = expf(ev - sc[0] * dd) + FEPS;
        int p = ((const int*)(g_s + POS_OFF))[e];
        g_s[EW_OFF + p] = ew;
        atomicAdd(&g_s[OUTW1_OFF + s], ew);
        atomicAdd(&g_s[INW1_OFF + d], ew);
    }
}

// ---------------- CSR aggregation layer1 (contiguous csr_src/ew) ----------------
__global__ void k_agg1(){
    int d = (blockIdx.x * blockDim.x + threadIdx.x) >> 5;
    int lane = threadIdx.x & 31;
    if (d >= NN) return;
    const int* rp = (const int*)(g_s + RP_OFF);
    const int* cs = (const int*)(g_s + CSRC_OFF);
    const float* ewc = g_s + EW_OFF;
    int b = rp[d], eend = rp[d + 1];
    float inw_r = rsqrtf(g_s[INW1_OFF + d]);
    float4 A = make_float4(0.f, 0.f, 0.f, 0.f);
    float4 Bc = make_float4(0.f, 0.f, 0.f, 0.f);
    int j = b;
    for (; j + 3 < eend; j += 4){
        int s0 = cs[j], s1 = cs[j + 1], s2 = cs[j + 2], s3 = cs[j + 3];
        float a0 = inw_r * rsqrtf(g_s[OUTW1_OFF + s0]) * ewc[j];
        float a1 = inw_r * rsqrtf(g_s[OUTW1_OFF + s1]) * ewc[j + 1];
        float a2 = inw_r * rsqrtf(g_s[OUTW1_OFF + s2]) * ewc[j + 2];
        float a3 = inw_r * rsqrtf(g_s[OUTW1_OFF + s3]) * ewc[j + 3];
        float4 h0 = ((const float4*)(g_s + H1_OFF + (size_t)s0 * NH))[lane];
        float4 h1 = ((const float4*)(g_s + H1_OFF + (size_t)s1 * NH))[lane];
        float4 h2 = ((const float4*)(g_s + H1_OFF + (size_t)s2 * NH))[lane];
        float4 h3 = ((const float4*)(g_s + H1_OFF + (size_t)s3 * NH))[lane];
        A.x = fmaf(h0.x, a0, A.x); A.y = fmaf(h0.y, a0, A.y);
        A.z = fmaf(h0.z, a0, A.z); A.w = fmaf(h0.w, a0, A.w);
        Bc.x = fmaf(h1.x, a1, Bc.x); Bc.y = fmaf(h1.y, a1, Bc.y);
        Bc.z = fmaf(h1.z, a1, Bc.z); Bc.w = fmaf(h1.w, a1, Bc.w);
        A.x = fmaf(h2.x, a2, A.x); A.y = fmaf(h2.y, a2, A.y);
        A.z = fmaf(h2.z, a2, A.z); A.w = fmaf(h2.w, a2, A.w);
        Bc.x = fmaf(h3.x, a3, Bc.x); Bc.y = fmaf(h3.y, a3, Bc.y);
        Bc.z = fmaf(h3.z, a3, Bc.z); Bc.w = fmaf(h3.w, a3, Bc.w);
    }
    for (; j < eend; j++){
        int s0 = cs[j];
        float a0 = inw_r * rsqrtf(g_s[OUTW1_OFF + s0]) * ewc[j];
        float4 h0 = ((const float4*)(g_s + H1_OFF + (size_t)s0 * NH))[lane];
        A.x = fmaf(h0.x, a0, A.x); A.y = fmaf(h0.y, a0, A.y);
        A.z = fmaf(h0.z, a0, A.z); A.w = fmaf(h0.w, a0, A.w);
    }
    float perm = g_s[SC_OFF + 3] / ((float)(eend - b) + FEPS);
    float4 hd = ((const float4*)(g_s + H1_OFF + (size_t)d * NH))[lane];
    float4 r;
    r.x = elu1(A.x + Bc.x + hd.x * perm);
    r.y = elu1(A.y + Bc.y + hd.y * perm);
    r.z = elu1(A.z + Bc.z + hd.z * perm);
    r.w = elu1(A.w + Bc.w + hd.w * perm);
    ((float4*)(g_s + RST1_OFF + (size_t)d * NH))[lane] = r;
}

// ---------------- GEMM2 (smem-tiled) + fused el2/er2 ----------------
__global__ __launch_bounds__(256) void k_gemm2n(const float* __restrict__ W,
                                                const float* __restrict__ wu,
                                                const float* __restrict__ wv){
    __shared__ float Ws[NH * NC];
    __shared__ float Rs[16][NH];
    int tid = threadIdx.x;
    for (int i = tid; i < NH * NC; i += 256) Ws[i] = W[i];
    int nb = blockIdx.x * 16;
#pragma unroll
    for (int it = 0; it < 8; it++){
        int i = tid + it * 256;
        int row = i >> 7, col = i & 127;
        Rs[row][col] = g_s[RST1_OFF + (size_t)(nb + row) * NH + col];
    }
    __syncthreads();
    int nl = tid >> 4, c = tid & 15;
    float acc = 0.f;
#pragma unroll
    for (int k = 0; k < NH; k++) acc = fmaf(Rs[nl][k], Ws[k * 16 + c], acc);
    int n = nb + nl;
    g_s[H2_OFF + (size_t)n * NC + c] = acc;
    float l = acc > 0.f ? acc : NEG * acc;
    float up = l * wu[c], vp = l * wv[c];
#pragma unroll
    for (int o = 8; o; o >>= 1){
        up += __shfl_xor_sync(0xffffffffu, up, o);
        vp += __shfl_xor_sync(0xffffffffu, vp, o);
    }
    if (c == 0){ g_s[EL2_OFF + n] = up; g_s[ER2_OFF + n] = vp; }
}

// ---------------- edge pass 2 (+ position loss fused) ----------------
__global__ void k_edge2(const int* __restrict__ src, const int* __restrict__ dst,
                        const float* __restrict__ ws, const float* __restrict__ lw){
    int e = blockIdx.x * blockDim.x + threadIdx.x;
    float lacc = 0.f;
    if (e < EE){
        int s = src[e], d = dst[e];
        const float4* hs = (const float4*)(g_s + H2_OFF + (size_t)s * NC);
        const float4* hd = (const float4*)(g_s + H2_OFF + (size_t)d * NC);
        const float4* fs = (const float4*)(g_s + HLATP2_OFF + (size_t)s * NC);
        const float4* fd = (const float4*)(g_s + HLATP2_OFF + (size_t)d * NC);
        const float4* w4 = (const float4*)ws;
        float sdf = 0.f, sds = 0.f, st = 0.f, pdot = 0.f;
#pragma unroll
        for (int j = 0; j < 4; j++){
            float4 a = hs[j], b = hd[j];
            float q;
            q = a.x - b.x; sdf += q * q;
            q = a.y - b.y; sdf += q * q;
            q = a.z - b.z; sdf += q * q;
            q = a.w - b.w; sdf += q * q;
            float4 p = fs[j], r = fd[j], w = w4[j];
            q = p.x - r.x; sds += q * q;
            q = p.y - r.y; sds += q * q;
            q = p.z - r.z; sds += q * q;
            q = p.w - r.w; sds += q * q;
            st += p.x * w.x * r.x + p.y * w.y * r.y + p.z * w.z * r.z + p.w * w.w * r.w;
            pdot += p.x * r.x + p.y * r.y + p.z * r.z + p.w * r.w;
        }
        const float* sc = g_s + SC_OFF;
        float ev = g_s[EL2_OFF + s] + g_s[ER2_OFF + d] + st;
        float ew = expf(ev - sc[4] * (sc[5] * sdf + sc[6] * sds)) + FEPS;
        int p = ((const int*)(g_s + POS_OFF))[e];
        g_s[EW_OFF + p] = ew;
        atomicAdd(&g_s[OUTW2_OFF + s], ew);
        atomicAdd(&g_s[INW2_OFF + d], ew);
        lacc = lw[e] * pdot;
    }
#pragma unroll
    for (int o = 16; o; o >>= 1) lacc += __shfl_xor_sync(0xffffffffu, lacc, o);
    if ((threadIdx.x & 31) == 0) atomicAdd(&g_s[LOSS_OFF], lacc);
}

// ---------------- CSR aggregation layer2 + final log-softmax ----------------
__global__ void k_agg2_final(float* __restrict__ out, int out_size){
    int d = (blockIdx.x * blockDim.x + threadIdx.x) >> 5;
    int lane = threadIdx.x & 31;
    if (d >= NN) return;
    if (d == 0 && lane == 0 && out_size > NN * NC) out[NN * NC] = g_s[LOSS_OFF];
    const int* rp = (const int*)(g_s + RP_OFF);
    const int* cs = (const int*)(g_s + CSRC_OFF);
    const float* ewc = g_s + EW_OFF;
    int b = rp[d], eend = rp[d + 1];
    int c = lane & 15;
    int half = lane >> 4;
    float inw_r = rsqrtf(g_s[INW2_OFF + d]);
    float acc = 0.f;
    for (int j = b + half; j < eend; j += 2){
        int s = cs[j];
        float a = inw_r * rsqrtf(g_s[OUTW2_OFF + s]) * ewc[j];
        acc = fmaf(g_s[H2_OFF + (size_t)s * NC + c], a, acc);
    }
    acc += __shfl_xor_sync(0xffffffffu, acc, 16);
    float perm = g_s[SC_OFF + 7] / ((float)(eend - b) + FEPS);
    float t = elu1(acc + g_s[H2_OFF + (size_t)d * NC + c] * perm);
    float mx = t;
#pragma unroll
    for (int o = 8; o; o >>= 1) mx = fmaxf(mx, __shfl_xor_sync(0xffffffffu, mx, o));
    float s2 = expf(t - mx);
#pragma unroll
    for (int o = 8; o; o >>= 1) s2 += __shfl_xor_sync(0xffffffffu, s2, o);
    float lse = mx + logf(s2);
    if (lane < 16) out[(size_t)d * NC + c] = t - lse;
}

// ---------------- launch ----------------
extern "C" void kernel_launch(void* const* d_in, const int* in_sizes, int n_in,
                              void* d_out, int out_size){
    const int*   src    = (const int*)  d_in[0];
    const int*   dst    = (const int*)  d_in[1];
    const float* x      = (const float*)d_in[2];
    const float* weights= (const float*)d_in[3];
    const float* latp   = (const float*)d_in[4];
    const float* sl_w   = (const float*)d_in[5];
    const float* sl_b   = (const float*)d_in[6];
    const float* slo_w  = (const float*)d_in[7];
    const float* slo_b  = (const float*)d_in[8];
    const float* fc1_w  = (const float*)d_in[9];
    const float* w_u1   = (const float*)d_in[10];
    const float* w_v1   = (const float*)d_in[11];
    const float* w_s1   = (const float*)d_in[12];
    const float* beta1  = (const float*)d_in[13];
    const float* aw1    = (const float*)d_in[14];
    const float* theta1 = (const float*)d_in[15];
    const float* fc2_w  = (const float*)d_in[16];
    const float* w_u2   = (const float*)d_in[17];
    const float* w_v2   = (const float*)d_in[18];
    const float* w_s2   = (const float*)d_in[19];
    const float* beta2  = (const float*)d_in[20];
    const float* aw2    = (const float*)d_in[21];
    const float* theta2 = (const float*)d_in[22];
    float* out = (float*)d_out;

    k_zero<<<1024, 256>>>(beta1, aw1, theta1, beta2, aw2, theta2);
    k_indeg<<<(EE + 255) / 256, 256>>>(dst);
    k_scanA<<<NBLK, 256>>>();
    k_scanB<<<NBLK, 256>>>();
    k_scatter<<<(EE + 255) / 256, 256>>>(src, dst);
    k_dense2x<<<(NN * NC + 255) / 256, 256>>>(latp, sl_w, sl_b, slo_w, slo_b);
    k_gemm1<<<(NN + 127) / 128, 256>>>(x, fc1_w, w_u1, w_v1);
    k_edge1<<<(EE * 8 + 255) / 256, 256>>>(src, dst, w_s1);
    k_agg1<<<(NN * 32 + 255) / 256, 256>>>();
    k_gemm2n<<<NN / 16, 256>>>(fc2_w, w_u2, w_v2);
    k_edge2<<<(EE + 255) / 256, 256>>>(src, dst, w_s2, weights);
    k_agg2_final<<<(NN * 32 + 255) / 256, 256>>>(out, out_size);
}